// round 1
// baseline (speedup 1.0000x reference)
#include <cuda_runtime.h>
#include <cuda_bf16.h>
#include <math.h>

// Problem constants
#define Bb   4
#define Tt   4096
#define Ww   1024
#define Hh   8
#define BW   128        // block width (channels per head)
#define TC   128        // tokens per tile / scan chunk
#define CC   (Tt / TC)  // chunks per sequence = 32
#define NW   256        // output cols per head tile (w_in | w_a)
#define XPAD 132        // padded M stride for transposed x tile (mult of 4, avoids bad banking)

// Scratch (device globals — no allocation allowed)
__device__ float g_a [Bb * Tt * Ww];   // decay coefficient a (post-reset)
__device__ float g_xn[Bb * Tt * Ww];   // normalized input x * gate_x * multiplier
__device__ float g_F [Bb * CC * Ww];   // per-chunk local scan final
__device__ float g_P [Bb * CC * Ww];   // per-chunk product of a
__device__ float g_H [Bb * CC * Ww];   // per-chunk carry-in h

// smem float offsets
#define SM_WS   0                       // [128][256] weights (w_in | w_a)       32768 floats
#define SM_XT   32768                   // [128][XPAD] x tile, transposed [k][m] 16896 floats
#define SM_SP   (SM_XT + 128 * XPAD)    // softplus(a_param) per channel          128
#define SM_BIA  (SM_SP + 128)           // biases b_in|b_a                        256
#define SM_RST  (SM_BIA + 256)          // keep factor (0 if reset else 1)        128
#define SM_FLOATS (SM_RST + 128)        // = 50176 floats
#define SMEM_BYTES (SM_FLOATS * 4)      // = 200704 B

// ---------------------------------------------------------------------------
// K1: fused block-diag GEMM (both gates) + elementwise + per-chunk local scan
// grid (TC-tiles per seq = 32, B = 4, H = 8), 256 threads
// ---------------------------------------------------------------------------
__global__ void __launch_bounds__(256, 1)
k_gates(const float* __restrict__ x, const int* __restrict__ segp,
        const float* __restrict__ a_param,
        const float* __restrict__ w_in, const float* __restrict__ b_in,
        const float* __restrict__ w_a,  const float* __restrict__ b_a)
{
    extern __shared__ float sm[];
    float* ws  = sm + SM_WS;
    float* xt  = sm + SM_XT;
    float* sp  = sm + SM_SP;
    float* bia = sm + SM_BIA;
    float* rst = sm + SM_RST;

    const int tid  = threadIdx.x;
    const int tile = blockIdx.x;       // chunk index within sequence
    const int b    = blockIdx.y;
    const int h    = blockIdx.z;
    const int t0   = tile * TC;

    // ---- load weights: ws[i][0..127] = w_in[h][i][:], ws[i][128..255] = w_a[h][i][:]
    {
        const float4* win4 = reinterpret_cast<const float4*>(w_in + h * BW * BW);
        const float4* wa4  = reinterpret_cast<const float4*>(w_a  + h * BW * BW);
        float4* ws4 = reinterpret_cast<float4*>(ws);
        #pragma unroll
        for (int it = 0; it < 16; ++it) {
            int f4 = tid + it * 256;           // 0..4095
            int i  = f4 >> 5;                  // input row
            int jq = f4 & 31;                  // float4 within row
            ws4[i * 64 + jq]      = win4[f4];
            ws4[i * 64 + 32 + jq] = wa4[f4];
        }
    }

    // ---- load x tile transposed: xt[k][m] ; global rows coalesced, smem conflict-free
    {
        const int warp = tid >> 5, lane = tid & 31;
        #pragma unroll
        for (int r = 0; r < 16; ++r) {
            int m = warp * 16 + r;
            const float* xr = x + (size_t)(b * Tt + t0 + m) * Ww + h * BW;
            #pragma unroll
            for (int j = 0; j < 4; ++j) {
                int k = lane + j * 32;
                xt[k * XPAD + m] = xr[k];
            }
        }
    }

    // ---- small per-channel / per-token data
    if (tid < 128) {
        sp[tid]  = log1pf(expf(a_param[h * BW + tid]));  // softplus(a_param)
        bia[tid] = b_in[h * BW + tid];
        rst[tid] = (segp[b * Tt + t0 + tid] == 0) ? 0.f : 1.f;
    } else {
        bia[tid] = b_a[h * BW + (tid - 128)];
    }
    __syncthreads();

    // ---- GEMM: z[128 tok][256 col] ; thread tile 8 tokens x 16 cols
    const int tx = tid & 15;           // col group
    const int ty = tid >> 4;           // token group
    const int m0 = ty * 8;

    float acc[8][16];
    #pragma unroll
    for (int i = 0; i < 8; ++i)
        #pragma unroll
        for (int n = 0; n < 16; ++n) acc[i][n] = 0.f;

    #pragma unroll 4
    for (int k = 0; k < 128; ++k) {
        float4 xa = *reinterpret_cast<const float4*>(&xt[k * XPAD + m0]);
        float4 xb = *reinterpret_cast<const float4*>(&xt[k * XPAD + m0 + 4]);
        float xv[8] = {xa.x, xa.y, xa.z, xa.w, xb.x, xb.y, xb.z, xb.w};
        float wv[16];
        #pragma unroll
        for (int q = 0; q < 4; ++q) {
            float4 wq = *reinterpret_cast<const float4*>(&ws[k * NW + q * 64 + tx * 4]);
            wv[q * 4 + 0] = wq.x; wv[q * 4 + 1] = wq.y;
            wv[q * 4 + 2] = wq.z; wv[q * 4 + 3] = wq.w;
        }
        #pragma unroll
        for (int i = 0; i < 8; ++i)
            #pragma unroll
            for (int n = 0; n < 16; ++n)
                acc[i][n] = fmaf(xv[i], wv[n], acc[i][n]);
    }
    __syncthreads();   // ws region about to be reused as gate staging

    // ---- stage sigmoids: gx[m][c] (cols 0..127), ga[m][c] (cols 128..255)
    float* gx = sm;            // 16384 floats (reuses ws)
    float* ga = sm + 16384;    // 16384 floats
    #pragma unroll
    for (int q = 0; q < 4; ++q) {
        #pragma unroll
        for (int j = 0; j < 4; ++j) {
            int col = q * 64 + tx * 4 + j;
            #pragma unroll
            for (int mi = 0; mi < 8; ++mi) {
                int m = m0 + mi;
                float z = acc[mi][q * 4 + j] + bia[col];
                float g = 1.f / (1.f + __expf(-z));
                if (col < 128) gx[m * 128 + col] = g;
                else           ga[m * 128 + (col - 128)] = g;
            }
        }
    }
    __syncthreads();

    // ---- elementwise: a = keep * exp(log_a), xn = x * gx * sqrt(-expm1(2 log_a))
    // write to global, and overwrite gx<-a, ga<-xn in place for the local scan
    const int gbase = (b * Tt + t0) * Ww + h * BW;
    #pragma unroll 4
    for (int it = 0; it < 64; ++it) {
        int idx = tid + it * 256;      // m*128 + c
        int m = idx >> 7;
        int c = idx & 127;
        float gxv = gx[idx];
        float gav = ga[idx];
        float la  = -8.f * gav * sp[c];
        float a   = expf(la) * rst[m];
        float mlt = sqrtf(fmaxf(-expm1f(2.f * la), 0.f));
        float xn  = xt[c * XPAD + m] * gxv * mlt;
        gx[idx] = a;
        ga[idx] = xn;
        int off = gbase + m * Ww + c;
        g_a[off]  = a;
        g_xn[off] = xn;
    }
    __syncthreads();

    // ---- per-chunk local scan: F (h with zero init) and P (prod of a)
    if (tid < 128) {
        const int c = tid;
        float hsum = 0.f, prod = 1.f;
        #pragma unroll 8
        for (int m = 0; m < TC; ++m) {
            float a  = gx[m * 128 + c];
            float xn = ga[m * 128 + c];
            hsum = fmaf(a, hsum, xn);
            prod *= a;
        }
        int off = ((b * CC + tile) << 10) + h * BW + c;
        g_F[off] = hsum;
        g_P[off] = prod;
    }
}

// ---------------------------------------------------------------------------
// K2: sequential carry propagation across chunks. 4096 independent sequences.
// ---------------------------------------------------------------------------
__global__ void k_carry()
{
    int idx = blockIdx.x * blockDim.x + threadIdx.x;
    if (idx >= Bb * Ww) return;
    int b = idx >> 10, w = idx & 1023;
    float carry = 0.f;
    #pragma unroll
    for (int c = 0; c < CC; ++c) {
        int off = ((b * CC + c) << 10) + w;
        g_H[off] = carry;
        carry = fmaf(g_P[off], carry, g_F[off]);
    }
}

// ---------------------------------------------------------------------------
// K3: apply — finish each chunk with its carry-in. Fully coalesced streaming.
// 131072 threads, each walks 128 timesteps of one (b, chunk, w).
// ---------------------------------------------------------------------------
__global__ void __launch_bounds__(256)
k_apply(float* __restrict__ out)
{
    int idx = blockIdx.x * blockDim.x + threadIdx.x;   // < B*CC*W = 131072
    int w  = idx & 1023;
    int bc = idx >> 10;                                // b*CC + chunk
    float hcur = g_H[idx];
    int base = (bc << 17) + w;                         // (b*CC+chunk)*TC*W + w
    #pragma unroll 4
    for (int m = 0; m < TC; ++m) {
        int off = base + (m << 10);
        hcur = fmaf(g_a[off], hcur, g_xn[off]);
        out[off] = hcur;
    }
}

// ---------------------------------------------------------------------------
extern "C" void kernel_launch(void* const* d_in, const int* in_sizes, int n_in,
                              void* d_out, int out_size)
{
    (void)in_sizes; (void)n_in; (void)out_size;
    const float* x       = (const float*)d_in[0];
    const int*   segp    = (const int*)  d_in[1];
    const float* a_param = (const float*)d_in[2];
    const float* w_in    = (const float*)d_in[3];
    const float* b_in    = (const float*)d_in[4];
    const float* w_a     = (const float*)d_in[5];
    const float* b_a     = (const float*)d_in[6];
    float* out = (float*)d_out;

    cudaFuncSetAttribute(k_gates, cudaFuncAttributeMaxDynamicSharedMemorySize,
                         SMEM_BYTES);

    k_gates<<<dim3(Tt / TC, Bb, Hh), 256, SMEM_BYTES>>>(
        x, segp, a_param, w_in, b_in, w_a, b_a);
    k_carry<<<(Bb * Ww + 255) / 256, 256>>>();
    k_apply<<<(Bb * CC * Ww) / 256, 256>>>(out);
}

// round 2
// speedup vs baseline: 1.1673x; 1.1673x over previous
#include <cuda_runtime.h>
#include <math.h>

// Problem constants
#define Bb   4
#define Tt   4096
#define Ww   1024
#define Hh   8
#define BW   128        // channels per head
#define TC   128        // tokens per tile / scan chunk
#define CC   (Tt / TC)  // chunks per sequence = 32
#define NW   256        // output cols per head tile (w_in | w_a)
#define XP   132        // padded m-stride for x tile [k][m]

// Scratch (device globals — no allocation allowed)
__device__ float g_a [Bb * Tt * Ww];
__device__ float g_xn[Bb * Tt * Ww];
__device__ float g_F [Bb * CC * Ww];
__device__ float g_P [Bb * CC * Ww];
__device__ float g_H [Bb * CC * Ww];

// smem float offsets
// [0, 32768)        ws [128][256]  (reused after GEMM as gx [0,16384) | ga [16384,32768))
// [32768, +16896)   xt [k][m] padded to XP=132
// then sp 128 | bia 256 | rst 128 | sF 512 | sP 512
#define SM_XT   32768
#define SM_SP   (SM_XT + 128 * XP)
#define SM_BIA  (SM_SP + 128)
#define SM_RST  (SM_BIA + 256)
#define SM_SF   (SM_RST + 128)
#define SM_SPP  (SM_SF + 512)
#define SM_TOT  (SM_SPP + 512)          // 51200 floats
#define SMEM_BYTES (SM_TOT * 4)         // 204800 B

// ---------------------------------------------------------------------------
// K1: fused block-diag GEMM (both gates) + elementwise + per-chunk local scan
// grid (32, 4, 8), 512 threads, 1 CTA/SM
// ---------------------------------------------------------------------------
__global__ void __launch_bounds__(512, 1)
k_gates(const float* __restrict__ x, const int* __restrict__ segp,
        const float* __restrict__ a_param,
        const float* __restrict__ w_in, const float* __restrict__ b_in,
        const float* __restrict__ w_a,  const float* __restrict__ b_a)
{
    extern __shared__ float sm[];
    float* ws  = sm;
    float* xt  = sm + SM_XT;
    float* sp  = sm + SM_SP;
    float* bia = sm + SM_BIA;
    float* rst = sm + SM_RST;
    float* sF  = sm + SM_SF;
    float* sP  = sm + SM_SPP;

    const int tid  = threadIdx.x;
    const int tile = blockIdx.x;
    const int b    = blockIdx.y;
    const int h    = blockIdx.z;
    const int t0   = tile * TC;

    // ---- weights: ws[i][0..127]=w_in[h][i][:], ws[i][128..255]=w_a[h][i][:]
    {
        const float4* win4 = reinterpret_cast<const float4*>(w_in + h * BW * BW);
        const float4* wa4  = reinterpret_cast<const float4*>(w_a  + h * BW * BW);
        float4* ws4 = reinterpret_cast<float4*>(ws);
        #pragma unroll
        for (int it = 0; it < 8; ++it) {
            int f4 = tid + it * 512;           // 0..4095
            int i  = f4 >> 5;
            int jq = f4 & 31;
            ws4[i * 64 + jq]      = win4[f4];
            ws4[i * 64 + 32 + jq] = wa4[f4];
        }
    }

    // ---- x tile transposed into [k][m] (global reads coalesced)
    {
        const int warp = tid >> 5, lane = tid & 31;
        #pragma unroll
        for (int r = 0; r < 8; ++r) {
            int m = warp * 8 + r;
            const float* xr = x + (size_t)(b * Tt + t0 + m) * Ww + h * BW;
            #pragma unroll
            for (int j = 0; j < 4; ++j) {
                int k = lane + j * 32;
                xt[k * XP + m] = xr[k];
            }
        }
    }

    // ---- per-channel / per-token small data
    if (tid < 128) {
        sp[tid]  = log1pf(expf(a_param[h * BW + tid]));
        bia[tid] = b_in[h * BW + tid];
        rst[tid] = (segp[b * Tt + t0 + tid] == 0) ? 0.f : 1.f;
    } else if (tid < 256) {
        bia[tid] = b_a[h * BW + (tid - 128)];
    }
    __syncthreads();

    // ---- GEMM: z[128 tok][256 col]; thread tile 8 tok x 8 col
    const int tx = tid & 31;          // col group: cols tx*8 .. tx*8+7
    const int ty = tid >> 5;          // token group (== warp): tokens ty*8..ty*8+7
    const int m0 = ty * 8;
    const int c0 = tx * 8;

    float acc[8][8];
    #pragma unroll
    for (int i = 0; i < 8; ++i)
        #pragma unroll
        for (int j = 0; j < 8; ++j) acc[i][j] = 0.f;

    #pragma unroll 4
    for (int k = 0; k < 128; ++k) {
        // x loads: all lanes in warp share m0 -> warp-broadcast LDS.128
        float4 xa = *reinterpret_cast<const float4*>(&xt[k * XP + m0]);
        float4 xb = *reinterpret_cast<const float4*>(&xt[k * XP + m0 + 4]);
        // w loads: lanes span contiguous 256-float row -> conflict-free
        float4 w0 = *reinterpret_cast<const float4*>(&ws[k * NW + c0]);
        float4 w1 = *reinterpret_cast<const float4*>(&ws[k * NW + c0 + 4]);
        float xv[8] = {xa.x, xa.y, xa.z, xa.w, xb.x, xb.y, xb.z, xb.w};
        float wv[8] = {w0.x, w0.y, w0.z, w0.w, w1.x, w1.y, w1.z, w1.w};
        #pragma unroll
        for (int i = 0; i < 8; ++i)
            #pragma unroll
            for (int j = 0; j < 8; ++j)
                acc[i][j] = fmaf(xv[i], wv[j], acc[i][j]);
    }

    // pull biases into regs before ws region is repurposed
    float bz[8];
    #pragma unroll
    for (int j = 0; j < 8; ++j) bz[j] = bia[c0 + j];
    __syncthreads();

    // ---- sigmoids -> staging: gx[m][c] (cols<128), ga[m][c] (cols>=128)
    float* gx = sm;            // 16384 floats
    float* ga = sm + 16384;    // 16384 floats
    {
        // each thread's 8 cols are all on one side of the 128 split
        float* dst = (c0 < 128) ? gx : (ga - 128);
        #pragma unroll
        for (int mi = 0; mi < 8; ++mi) {
            float g[8];
            #pragma unroll
            for (int j = 0; j < 8; ++j) {
                float z = acc[mi][j] + bz[j];
                g[j] = __fdividef(1.f, 1.f + __expf(-z));
            }
            float* p = &dst[(m0 + mi) * 128 + c0];
            *reinterpret_cast<float4*>(p)     = make_float4(g[0], g[1], g[2], g[3]);
            *reinterpret_cast<float4*>(p + 4) = make_float4(g[4], g[5], g[6], g[7]);
        }
    }
    __syncthreads();

    // ---- elementwise: a = keep*exp(log_a), xn = x*gx*sqrt(-expm1(2*log_a))
    const int gbase = (b * Tt + t0) * Ww + h * BW;
    #pragma unroll 4
    for (int it = 0; it < 32; ++it) {
        int idx = tid + it * 512;      // m*128 + c
        int m = idx >> 7;
        int c = idx & 127;
        float gxv = gx[idx];
        float gav = ga[idx];
        float la  = -8.f * gav * sp[c];
        float a   = expf(la) * rst[m];
        float mlt = sqrtf(fmaxf(-expm1f(2.f * la), 0.f));
        float xn  = xt[c * XP + m] * gxv * mlt;      // 4-way bank conflict, cheap
        gx[idx] = a;                                  // in-place: own idx only
        ga[idx] = xn;
        int off = gbase + m * Ww + c;
        g_a[off]  = a;
        g_xn[off] = xn;
    }
    __syncthreads();

    // ---- per-chunk local scan, 4-way split over token segments
    {
        const int c = tid & 127;
        const int s = tid >> 7;            // segment 0..3 (32 tokens each)
        float hs = 0.f, pr = 1.f;
        const int mb = s * 32;
        #pragma unroll 8
        for (int mi = 0; mi < 32; ++mi) {
            int m = mb + mi;
            float a  = gx[m * 128 + c];
            float xn = ga[m * 128 + c];
            hs = fmaf(a, hs, xn);
            pr *= a;
        }
        sF[s * 128 + c] = hs;
        sP[s * 128 + c] = pr;
    }
    __syncthreads();
    if (tid < 128) {
        float F = sF[tid], P = sP[tid];
        #pragma unroll
        for (int s = 1; s < 4; ++s) {
            float ps = sP[s * 128 + tid];
            F = fmaf(ps, F, sF[s * 128 + tid]);
            P *= ps;
        }
        int off = ((b * CC + tile) << 10) + h * BW + tid;
        g_F[off] = F;
        g_P[off] = P;
    }
}

// ---------------------------------------------------------------------------
// K2: sequential carry propagation across chunks (4096 independent scans)
// ---------------------------------------------------------------------------
__global__ void k_carry()
{
    int idx = blockIdx.x * blockDim.x + threadIdx.x;
    if (idx >= Bb * Ww) return;
    int b = idx >> 10, w = idx & 1023;
    float carry = 0.f;
    #pragma unroll
    for (int c = 0; c < CC; ++c) {
        int off = ((b * CC + c) << 10) + w;
        g_H[off] = carry;
        carry = fmaf(g_P[off], carry, g_F[off]);
    }
}

// ---------------------------------------------------------------------------
// K3: apply carry-ins; fully coalesced streaming
// ---------------------------------------------------------------------------
__global__ void __launch_bounds__(256)
k_apply(float* __restrict__ out)
{
    int idx = blockIdx.x * blockDim.x + threadIdx.x;   // < B*CC*W = 131072
    int w  = idx & 1023;
    int bc = idx >> 10;
    float hcur = g_H[idx];
    int base = (bc << 17) + w;
    #pragma unroll 4
    for (int m = 0; m < TC; ++m) {
        int off = base + (m << 10);
        hcur = fmaf(g_a[off], hcur, g_xn[off]);
        out[off] = hcur;
    }
}

// ---------------------------------------------------------------------------
extern "C" void kernel_launch(void* const* d_in, const int* in_sizes, int n_in,
                              void* d_out, int out_size)
{
    (void)in_sizes; (void)n_in; (void)out_size;
    const float* x       = (const float*)d_in[0];
    const int*   segp    = (const int*)  d_in[1];
    const float* a_param = (const float*)d_in[2];
    const float* w_in    = (const float*)d_in[3];
    const float* b_in    = (const float*)d_in[4];
    const float* w_a     = (const float*)d_in[5];
    const float* b_a     = (const float*)d_in[6];
    float* out = (float*)d_out;

    cudaFuncSetAttribute(k_gates, cudaFuncAttributeMaxDynamicSharedMemorySize,
                         SMEM_BYTES);

    k_gates<<<dim3(Tt / TC, Bb, Hh), 512, SMEM_BYTES>>>(
        x, segp, a_param, w_in, b_in, w_a, b_a);
    k_carry<<<(Bb * Ww + 255) / 256, 256>>>();
    k_apply<<<(Bb * CC * Ww) / 256, 256>>>(out);
}

// round 4
// speedup vs baseline: 1.2486x; 1.0696x over previous
#include <cuda_runtime.h>
#include <math.h>

// Problem constants
#define Bb   4
#define Tt   4096
#define Ww   1024
#define Hh   8
#define BW   128        // channels per head
#define TC   128        // tokens per tile / scan chunk
#define CC   (Tt / TC)  // chunks per sequence = 32
#define NW   256        // output cols per head tile (w_in | w_a)
#define XP   132        // padded m-stride for x tile [k][m]

// Scratch (device globals — no allocation allowed)
__device__ float g_a [Bb * Tt * Ww];
__device__ float g_xn[Bb * Tt * Ww];
__device__ float g_F [Bb * CC * Ww];
__device__ float g_P [Bb * CC * Ww];
__device__ float g_H [Bb * CC * Ww];

// smem float offsets
// [0, 32768)        ws [128][256]  (reused after GEMM: sA [0,16384) | sX [16384,32768))
// [32768, +16896)   xt [k][m] padded to XP=132
// then sp 128 | bia 256 | rst 128 | sF 512 | sP 512
#define SM_XT   32768
#define SM_SP   (SM_XT + 128 * XP)
#define SM_BIA  (SM_SP + 128)
#define SM_RST  (SM_BIA + 256)
#define SM_SF   (SM_RST + 128)
#define SM_SPP  (SM_SF + 512)
#define SM_TOT  (SM_SPP + 512)
#define SMEM_BYTES (SM_TOT * 4)         // 204800 B

// ---------------------------------------------------------------------------
// K1: fused block-diag GEMM (both gates) + elementwise epilogue + local scan
// grid (32, 4, 8), 512 threads, 1 CTA/SM
// Thread tile: 8 tokens x (4 gate_x cols + 4 gate_a cols, SAME channels)
// ---------------------------------------------------------------------------
__global__ void __launch_bounds__(512, 1)
k_gates(const float* __restrict__ x, const int* __restrict__ segp,
        const float* __restrict__ a_param,
        const float* __restrict__ w_in, const float* __restrict__ b_in,
        const float* __restrict__ w_a,  const float* __restrict__ b_a)
{
    extern __shared__ float sm[];
    float* ws  = sm;
    float* xt  = sm + SM_XT;
    float* sp  = sm + SM_SP;
    float* bia = sm + SM_BIA;
    float* rst = sm + SM_RST;
    float* sF  = sm + SM_SF;
    float* sP  = sm + SM_SPP;

    const int tid  = threadIdx.x;
    const int tile = blockIdx.x;
    const int b    = blockIdx.y;
    const int h    = blockIdx.z;
    const int t0   = tile * TC;

    // ---- weights: ws[i][0..127]=w_in[h][i][:], ws[i][128..255]=w_a[h][i][:]
    {
        const float4* win4 = reinterpret_cast<const float4*>(w_in + h * BW * BW);
        const float4* wa4  = reinterpret_cast<const float4*>(w_a  + h * BW * BW);
        float4* ws4 = reinterpret_cast<float4*>(ws);
        #pragma unroll
        for (int it = 0; it < 8; ++it) {
            int f4 = tid + it * 512;           // 0..4095
            int i  = f4 >> 5;
            int jq = f4 & 31;
            ws4[i * 64 + jq]      = win4[f4];
            ws4[i * 64 + 32 + jq] = wa4[f4];
        }
    }

    // ---- x tile transposed into [k][m] (global reads coalesced)
    {
        const int warp = tid >> 5, lane = tid & 31;
        #pragma unroll
        for (int r = 0; r < 8; ++r) {
            int m = warp * 8 + r;
            const float* xr = x + (size_t)(b * Tt + t0 + m) * Ww + h * BW;
            #pragma unroll
            for (int j = 0; j < 4; ++j) {
                int k = lane + j * 32;
                xt[k * XP + m] = xr[k];
            }
        }
    }

    // ---- per-channel / per-token small data
    if (tid < 128) {
        sp[tid]  = log1pf(expf(a_param[h * BW + tid]));
        bia[tid] = b_in[h * BW + tid];
        rst[tid] = (segp[b * Tt + t0 + tid] == 0) ? 0.f : 1.f;
    } else if (tid < 256) {
        bia[tid] = b_a[h * BW + (tid - 128)];
    }
    __syncthreads();

    // ---- GEMM: z[128 tok][256 col]
    // lane tx -> cols [tx*4, tx*4+4) (gate_x) and [128+tx*4, ...) (gate_a)
    // both w loads are lane-contiguous (dense 512B per warp) -> no waste
    const int tx = tid & 31;
    const int ty = tid >> 5;          // warp id; tokens ty*8..ty*8+7
    const int m0 = ty * 8;
    const int c0 = tx * 4;

    float acc[8][8];
    #pragma unroll
    for (int i = 0; i < 8; ++i)
        #pragma unroll
        for (int j = 0; j < 8; ++j) acc[i][j] = 0.f;

    #pragma unroll 4
    for (int k = 0; k < 128; ++k) {
        // x: warp-uniform m0 -> broadcast LDS
        float4 xa = *reinterpret_cast<const float4*>(&xt[k * XP + m0]);
        float4 xb = *reinterpret_cast<const float4*>(&xt[k * XP + m0 + 4]);
        // w: dense contiguous across lanes
        float4 w0 = *reinterpret_cast<const float4*>(&ws[k * NW + c0]);
        float4 w1 = *reinterpret_cast<const float4*>(&ws[k * NW + 128 + c0]);
        float xv[8] = {xa.x, xa.y, xa.z, xa.w, xb.x, xb.y, xb.z, xb.w};
        float wv[8] = {w0.x, w0.y, w0.z, w0.w, w1.x, w1.y, w1.z, w1.w};
        #pragma unroll
        for (int i = 0; i < 8; ++i)
            #pragma unroll
            for (int j = 0; j < 8; ++j)
                acc[i][j] = fmaf(xv[i], wv[j], acc[i][j]);
    }

    // pull per-column constants into regs before ws region is repurposed
    float bz0[4], bz1[4], sp4[4];
    #pragma unroll
    for (int j = 0; j < 4; ++j) {
        bz0[j] = bia[c0 + j];
        bz1[j] = bia[128 + c0 + j];
        sp4[j] = sp[c0 + j];
    }
    __syncthreads();

    // ---- fused epilogue: sigmoids + a/mult/xn in registers, write once
    float* sA = sm;            // a  [m][c], 16384 floats (reuses ws)
    float* sX = sm + 16384;    // xn [m][c]
    {
        const float* xrow = x + (size_t)(b * Tt + t0) * Ww + h * BW + c0;
        float* ga_out = g_a  + (size_t)(b * Tt + t0) * Ww + h * BW + c0;
        float* gx_out = g_xn + (size_t)(b * Tt + t0) * Ww + h * BW + c0;
        #pragma unroll
        for (int mi = 0; mi < 8; ++mi) {
            const int m = m0 + mi;
            float4 xg = *reinterpret_cast<const float4*>(xrow + (size_t)m * Ww);
            float keep = rst[m];
            float av[4], xnv[4];
            #pragma unroll
            for (int j = 0; j < 4; ++j) {
                float zx  = acc[mi][j]     + bz0[j];
                float za  = acc[mi][j + 4] + bz1[j];
                float gxv = __fdividef(1.f, 1.f + __expf(-zx));
                float gav = __fdividef(1.f, 1.f + __expf(-za));
                float la  = -8.f * gav * sp4[j];
                float a   = expf(la) * keep;
                float mlt = sqrtf(fmaxf(-expm1f(2.f * la), 0.f));
                av[j]  = a;
                xnv[j] = (&xg.x)[j] * gxv * mlt;
            }
            float4 a4  = make_float4(av[0],  av[1],  av[2],  av[3]);
            float4 xn4 = make_float4(xnv[0], xnv[1], xnv[2], xnv[3]);
            *reinterpret_cast<float4*>(&sA[m * 128 + c0]) = a4;
            *reinterpret_cast<float4*>(&sX[m * 128 + c0]) = xn4;
            *reinterpret_cast<float4*>(ga_out + (size_t)m * Ww) = a4;
            *reinterpret_cast<float4*>(gx_out + (size_t)m * Ww) = xn4;
        }
    }
    __syncthreads();

    // ---- per-chunk local scan, 4-way split over token segments
    {
        const int c = tid & 127;
        const int s = tid >> 7;            // segment 0..3 (32 tokens each)
        float hs = 0.f, pr = 1.f;
        const int mb = s * 32;
        #pragma unroll 8
        for (int mi = 0; mi < 32; ++mi) {
            int m = mb + mi;
            float a  = sA[m * 128 + c];
            float xn = sX[m * 128 + c];
            hs = fmaf(a, hs, xn);
            pr *= a;
        }
        sF[s * 128 + c] = hs;
        sP[s * 128 + c] = pr;
    }
    __syncthreads();
    if (tid < 128) {
        float F = sF[tid], P = sP[tid];
        #pragma unroll
        for (int s = 1; s < 4; ++s) {
            float ps = sP[s * 128 + tid];
            F = fmaf(ps, F, sF[s * 128 + tid]);
            P *= ps;
        }
        int off = ((b * CC + tile) << 10) + h * BW + tid;
        g_F[off] = F;
        g_P[off] = P;
    }
}

// ---------------------------------------------------------------------------
// K2: sequential carry propagation across chunks (4096 independent scans)
// ---------------------------------------------------------------------------
__global__ void k_carry()
{
    int idx = blockIdx.x * blockDim.x + threadIdx.x;
    if (idx >= Bb * Ww) return;
    int b = idx >> 10, w = idx & 1023;
    float carry = 0.f;
    #pragma unroll
    for (int c = 0; c < CC; ++c) {
        int off = ((b * CC + c) << 10) + w;
        g_H[off] = carry;
        carry = fmaf(g_P[off], carry, g_F[off]);
    }
}

// ---------------------------------------------------------------------------
// K3: apply carry-ins; fully coalesced streaming
// ---------------------------------------------------------------------------
__global__ void __launch_bounds__(256)
k_apply(float* __restrict__ out)
{
    int idx = blockIdx.x * blockDim.x + threadIdx.x;   // < B*CC*W = 131072
    int w  = idx & 1023;
    int bc = idx >> 10;
    float hcur = g_H[idx];
    int base = (bc << 17) + w;
    #pragma unroll 4
    for (int m = 0; m < TC; ++m) {
        int off = base + (m << 10);
        hcur = fmaf(g_a[off], hcur, g_xn[off]);
        out[off] = hcur;
    }
}

// ---------------------------------------------------------------------------
extern "C" void kernel_launch(void* const* d_in, const int* in_sizes, int n_in,
                              void* d_out, int out_size)
{
    (void)in_sizes; (void)n_in; (void)out_size;
    const float* x       = (const float*)d_in[0];
    const int*   segp    = (const int*)  d_in[1];
    const float* a_param = (const float*)d_in[2];
    const float* w_in    = (const float*)d_in[3];
    const float* b_in    = (const float*)d_in[4];
    const float* w_a     = (const float*)d_in[5];
    const float* b_a     = (const float*)d_in[6];
    float* out = (float*)d_out;

    cudaFuncSetAttribute(k_gates, cudaFuncAttributeMaxDynamicSharedMemorySize,
                         SMEM_BYTES);

    k_gates<<<dim3(Tt / TC, Bb, Hh), 512, SMEM_BYTES>>>(
        x, segp, a_param, w_in, b_in, w_a, b_a);
    k_carry<<<(Bb * Ww + 255) / 256, 256>>>();
    k_apply<<<(Bb * CC * Ww) / 256, 256>>>(out);
}